// round 3
// baseline (speedup 1.0000x reference)
#include <cuda_runtime.h>
#include <cuda_fp16.h>
#include <math.h>

#define BB 2
#define NQ 256
#define NK 2048
#define DIM 256
#define NH 8
#define HD 32
#define NPTS 8
#define NCELL 1000

#define ATT_THREADS 512
#define KPT (NK / ATT_THREADS)   // 4

// scratch (device globals — no allocation allowed)
__device__ __half g_tables[NPTS * NCELL * NH];  // [i][cell=z*100+y*10+x][h], fp16
__device__ float g_qproj[BB * NQ * DIM];        // [b*NQ+q][h*32+d]
__device__ float g_kproj[BB * NK * HD];
__device__ float g_vproj[BB * NK * HD];
__device__ float g_xmid [BB * NQ * DIM];

// -------------------- CPB tables --------------------
__global__ void k_tables(const float* __restrict__ w1, const float* __restrict__ b1,
                         const float* __restrict__ w2) {
    int gid = blockIdx.x * blockDim.x + threadIdx.x;
    if (gid >= NPTS * NCELL) return;
    int i = gid / NCELL;
    int cell = gid % NCELL;
    int p = cell / 100, q = (cell / 10) % 10, r = cell % 10;
    const float step = 8.0f / 9.0f;
    float lp = -4.0f + p * step, lq = -4.0f + q * step, lr = -4.0f + r * step;
    const float* w1i = w1 + i * 3 * 128;
    const float* b1i = b1 + i * 128;
    const float* w2i = w2 + i * 128 * 8;
    float acc[8] = {0,0,0,0,0,0,0,0};
    for (int d = 0; d < 128; d++) {
        float h = lp * w1i[d] + lq * w1i[128 + d] + lr * w1i[256 + d] + b1i[d];
        h = fmaxf(h, 0.0f);
        const float* w2d = w2i + d * 8;
        #pragma unroll
        for (int hh = 0; hh < 8; hh++) acc[hh] += h * w2d[hh];
    }
    __half* out = g_tables + gid * 8;
    #pragma unroll
    for (int hh = 0; hh < 8; hh++) out[hh] = __float2half(acc[hh]);
}

// -------------------- Q projection: 8 rows per block --------------------
__global__ void k_qproj(const float* __restrict__ query, const float* __restrict__ w,
                        const float* __restrict__ bias) {
    __shared__ float rows[8][DIM];       // 8 KB
    int blk = blockIdx.x;                // 64 blocks: b*32 + qgroup
    int b = blk >> 5, qbase = (blk & 31) * 8;
    int t = threadIdx.x;                 // 256
    #pragma unroll
    for (int r = 0; r < 8; r++)
        rows[r][t] = query[((qbase + r) * BB + b) * DIM + t];  // (nQ, B, DIM)
    __syncthreads();
    float acc[8];
    float bj = bias[t];
    #pragma unroll
    for (int r = 0; r < 8; r++) acc[r] = bj;
    for (int c = 0; c < DIM; c++) {
        float wv = w[c * DIM + t];
        #pragma unroll
        for (int r = 0; r < 8; r++) acc[r] += rows[r][c] * wv;
    }
    #pragma unroll
    for (int r = 0; r < 8; r++)
        g_qproj[((b << 8) + qbase + r) * DIM + t] = acc[r];
}

// -------------------- K/V projection: 16 rows per block --------------------
__global__ void k_kvproj(const float* __restrict__ key,
                         const float* __restrict__ kw, const float* __restrict__ kb,
                         const float* __restrict__ vw, const float* __restrict__ vb) {
    __shared__ float rows[16][DIM];      // 16 KB
    int blk = blockIdx.x;                // 256 blocks: b*128 + kgroup
    int b = blk >> 7, kbase = (blk & 127) * 16;
    int t = threadIdx.x;                 // 256
    for (int idx = t; idx < 16 * DIM; idx += 256) {
        int r = idx >> 8, c = idx & 255;
        rows[r][c] = key[((kbase + r) * BB + b) * DIM + c];
    }
    __syncthreads();
    int j = t & 31;
    int which = (t >> 5) & 1;            // 0 = K, 1 = V  (warp-uniform)
    int rg = t >> 6;                     // row group 0..3 (warp-uniform)
    const float* w = which ? vw : kw;
    float bj = which ? vb[j] : kb[j];
    float acc[4] = {bj, bj, bj, bj};
    for (int c = 0; c < DIM; c++) {
        float wv = w[c * HD + j];
        #pragma unroll
        for (int r = 0; r < 4; r++) acc[r] += rows[rg * 4 + r][c] * wv;
    }
    float* dst = which ? g_vproj : g_kproj;
    #pragma unroll
    for (int r = 0; r < 4; r++)
        dst[(b * NK + kbase + rg * 4 + r) * HD + j] = acc[r];
}

// -------------------- attention megakernel --------------------
__device__ __forceinline__ float xform(float dd) {
    float g = __log2f(fabsf(dd) * 512.0f + 1.0f) * (1.0f / 12.0f);
    return copysignf(g, dd);
}

__device__ __forceinline__ void axis_setup(float f, int scale, int* o, float* w) {
    float f0 = floorf(f);
    int i0 = (int)f0;
    float w1 = f - f0;
    int c0 = min(max(i0, 0), 9);
    int c1 = min(max(i0 + 1, 0), 9);
    o[0] = c0 * scale;
    o[1] = c1 * scale;
    w[0] = ((unsigned)i0 < 10u) ? 1.0f - w1 : 0.0f;
    w[1] = ((unsigned)(i0 + 1) < 10u) ? w1 : 0.0f;
}

// smem layout:
//   s_tbl   : __half[64000] = 128000 B
//   s_scores: float[NH*NK]  = 65536 B
//   s_q, s_rp, s_red
#define SM_TBL_HALVES (NPTS * NCELL * NH)          // 64000
#define SM_SCORES_OFF (SM_TBL_HALVES / 2)          // floats: 32000
#define SM_Q_OFF      (SM_SCORES_OFF + NH * NK)
#define SM_RP_OFF     (SM_Q_OFF + DIM)
#define SM_RED_OFF    (SM_RP_OFF + 24)
#define SM_TOTAL_F    (SM_RED_OFF + 400)

__global__ void __launch_bounds__(ATT_THREADS, 1)
k_attn(const float* __restrict__ refpt, const float* __restrict__ xyz,
       float* __restrict__ out_attn) {
    extern __shared__ float sm[];
    __half* s_tbl   = (__half*)sm;
    float* s_scores = sm + SM_SCORES_OFF;
    float* s_q      = sm + SM_Q_OFF;
    float* s_rp     = sm + SM_RP_OFF;
    float* s_red    = sm + SM_RED_OFF;

    int t = threadIdx.x;
    int bq = blockIdx.x;
    int b = bq >> 8, nq = bq & 255;

    if (t < DIM) s_q[t]  = g_qproj[bq * DIM + t];
    if (t < 24)  s_rp[t] = refpt[bq * 24 + t];

    // stage all 8 tables (fp16, 128000 B) into smem
    {
        const uint4* src = (const uint4*)g_tables;
        uint4* dst = (uint4*)s_tbl;
        const int n16 = SM_TBL_HALVES * 2 / 16;
        for (int idx = t; idx < n16; idx += ATT_THREADS) dst[idx] = src[idx];
    }
    __syncthreads();

    const float4* s_q4 = (const float4*)s_q;
    const float scale = 0.17677669529663687f;     // 1/sqrt(32)

    float runmax[NH];
    #pragma unroll
    for (int h = 0; h < NH; h++) runmax[h] = -1e30f;

    // ---- QK^T + RPE (single pass over k) ----
    #pragma unroll
    for (int m = 0; m < KPT; m++) {
        int k = t + m * ATT_THREADS;
        const float* kv = g_kproj + (b * NK + k) * HD;
        float kvv[HD];
        #pragma unroll
        for (int d = 0; d < HD; d += 4) {
            float4 f = *(const float4*)(kv + d);
            kvv[d] = f.x; kvv[d+1] = f.y; kvv[d+2] = f.z; kvv[d+3] = f.w;
        }
        const float* xv = xyz + (b * NK + k) * 3;
        float kx = xv[0], ky = xv[1], kz = xv[2];

        float acc[NH];
        #pragma unroll
        for (int h = 0; h < NH; h++) {
            float a = 0.f;
            #pragma unroll
            for (int d4 = 0; d4 < HD / 4; d4++) {
                float4 q = s_q4[h * (HD / 4) + d4];
                a += q.x * kvv[d4 * 4 + 0];
                a += q.y * kvv[d4 * 4 + 1];
                a += q.z * kvv[d4 * 4 + 2];
                a += q.w * kvv[d4 * 4 + 3];
            }
            acc[h] = a * scale;
        }

        // RPE accumulate in fp16 across 8 tables x 8 corners
        __half2 hacc0 = __float2half2_rn(0.f);
        __half2 hacc1 = hacc0, hacc2 = hacc0, hacc3 = hacc0;
        #pragma unroll
        for (int i = 0; i < NPTS; i++) {
            float gx = xform(s_rp[i*3+0] - kx);
            float gy = xform(s_rp[i*3+1] - ky);
            float gz = xform(s_rp[i*3+2] - kz);
            float fx = fmaf(gx, 4.5f, 4.5f);
            float fy = fmaf(gy, 4.5f, 4.5f);
            float fz = fmaf(gz, 4.5f, 4.5f);
            int oxa[2], oya[2], oza[2];
            float wxa[2], wya[2], wza[2];
            axis_setup(fx, NH,        oxa, wxa);
            axis_setup(fy, NH * 10,   oya, wya);
            axis_setup(fz, NH * 100,  oza, wza);
            float wzy[4] = {wza[0]*wya[0], wza[0]*wya[1], wza[1]*wya[0], wza[1]*wya[1]};
            const __half* base = s_tbl + i * (NCELL * NH);
            // batched unconditional loads (MLP=8)
            uint4 raw[8];
            #pragma unroll
            for (int c = 0; c < 8; c++)
                raw[c] = *(const uint4*)(base + oza[c >> 2] + oya[(c >> 1) & 1] + oxa[c & 1]);
            #pragma unroll
            for (int c = 0; c < 8; c++) {
                float w = wzy[c >> 1] * wxa[c & 1];
                __half2 wh = __float2half2_rn(w);
                __half2 v0 = *(const __half2*)&raw[c].x;
                __half2 v1 = *(const __half2*)&raw[c].y;
                __half2 v2 = *(const __half2*)&raw[c].z;
                __half2 v3 = *(const __half2*)&raw[c].w;
                hacc0 = __hfma2(wh, v0, hacc0);
                hacc1 = __hfma2(wh, v1, hacc1);
                hacc2 = __hfma2(wh, v2, hacc2);
                hacc3 = __hfma2(wh, v3, hacc3);
            }
        }
        float2 f0 = __half22float2(hacc0);
        float2 f1 = __half22float2(hacc1);
        float2 f2 = __half22float2(hacc2);
        float2 f3 = __half22float2(hacc3);
        acc[0] += f0.x; acc[1] += f0.y;
        acc[2] += f1.x; acc[3] += f1.y;
        acc[4] += f2.x; acc[5] += f2.y;
        acc[6] += f3.x; acc[7] += f3.y;

        #pragma unroll
        for (int h = 0; h < NH; h++) {
            s_scores[h * NK + k] = acc[h];
            runmax[h] = fmaxf(runmax[h], acc[h]);
        }
    }

    // ---- softmax ----
    int lane = t & 31, wid = t >> 5;  // 16 warps
    #pragma unroll
    for (int h = 0; h < NH; h++) {
        float v = runmax[h];
        #pragma unroll
        for (int o = 16; o; o >>= 1) v = fmaxf(v, __shfl_xor_sync(0xffffffffu, v, o));
        if (lane == 0) s_red[h * 16 + wid] = v;
    }
    __syncthreads();
    if (t < NH) {
        float v = s_red[t * 16];
        for (int w2 = 1; w2 < 16; w2++) v = fmaxf(v, s_red[t * 16 + w2]);
        s_red[128 + t] = v;
    }
    __syncthreads();
    #pragma unroll
    for (int h = 0; h < NH; h++) {
        float mh = s_red[128 + h];
        float v = 0.f;
        #pragma unroll
        for (int m = 0; m < KPT; m++) {
            int k = t + m * ATT_THREADS;
            float e = __expf(s_scores[h * NK + k] - mh);
            s_scores[h * NK + k] = e;              // unnormalized
            v += e;
        }
        #pragma unroll
        for (int o = 16; o; o >>= 1) v += __shfl_xor_sync(0xffffffffu, v, o);
        if (lane == 0) s_red[h * 16 + wid] = v;
    }
    __syncthreads();
    if (t < NH) {
        float v = 0.f;
        for (int w2 = 0; w2 < 16; w2++) v += s_red[t * 16 + w2];
        s_red[136 + t] = 1.0f / v;
    }
    __syncthreads();

    // ---- write normalized attn to gmem (smem keeps unnormalized e) ----
    #pragma unroll
    for (int h = 0; h < NH; h++) {
        float r = s_red[136 + h];
        #pragma unroll
        for (int m = 0; m < KPT; m++) {
            int k = t + m * ATT_THREADS;
            out_attn[((size_t)(b * NH + h) * NQ + nq) * NK + k] = s_scores[h * NK + k] * r;
        }
    }

    // ---- AV on unnormalized e, scale at end ----
    int half = t >> 8;
    int idx  = t & 255;
    int h = idx >> 5, d = idx & 31;
    float rinv = s_red[136 + h];
    float acc = 0.f;
    const float* vbase = g_vproj + b * NK * HD;
    int k0 = half * (NK / 2);
    int k1 = k0 + (NK / 2);
    for (; k0 < k1; k0 += 8) {
        float4 p0 = *(const float4*)&s_scores[h * NK + k0];
        float4 p1 = *(const float4*)&s_scores[h * NK + k0 + 4];
        float v0 = vbase[(k0 + 0) * HD + d];
        float v1 = vbase[(k0 + 1) * HD + d];
        float v2 = vbase[(k0 + 2) * HD + d];
        float v3 = vbase[(k0 + 3) * HD + d];
        float v4 = vbase[(k0 + 4) * HD + d];
        float v5 = vbase[(k0 + 5) * HD + d];
        float v6 = vbase[(k0 + 6) * HD + d];
        float v7 = vbase[(k0 + 7) * HD + d];
        acc += p0.x * v0 + p0.y * v1 + p0.z * v2 + p0.w * v3;
        acc += p1.x * v4 + p1.y * v5 + p1.z * v6 + p1.w * v7;
    }
    acc *= rinv;
    if (half) s_red[144 + idx] = acc;
    __syncthreads();
    if (!half) g_xmid[bq * DIM + idx] = acc + s_red[144 + idx];
}

// -------------------- output projection: 8 rows per block --------------------
__global__ void k_proj(const float* __restrict__ w, const float* __restrict__ bias,
                       float* __restrict__ out_x) {
    __shared__ float rows[8][DIM];
    int blk = blockIdx.x;                // 64 blocks
    int b = blk >> 5, qbase = (blk & 31) * 8;
    int t = threadIdx.x;
    #pragma unroll
    for (int r = 0; r < 8; r++)
        rows[r][t] = g_xmid[((b << 8) + qbase + r) * DIM + t];
    __syncthreads();
    float acc[8];
    float bj = bias[t];
    #pragma unroll
    for (int r = 0; r < 8; r++) acc[r] = bj;
    for (int c = 0; c < DIM; c++) {
        float wv = w[c * DIM + t];
        #pragma unroll
        for (int r = 0; r < 8; r++) acc[r] += rows[r][c] * wv;
    }
    #pragma unroll
    for (int r = 0; r < 8; r++)
        out_x[((qbase + r) * BB + b) * DIM + t] = acc[r];
}

// -------------------- launch --------------------
extern "C" void kernel_launch(void* const* d_in, const int* in_sizes, int n_in,
                              void* d_out, int out_size) {
    const float* query = (const float*)d_in[0];
    const float* key   = (const float*)d_in[1];
    const float* refpt = (const float*)d_in[2];
    const float* xyz   = (const float*)d_in[4];
    const float* q_w   = (const float*)d_in[5];
    const float* q_b   = (const float*)d_in[6];
    const float* k_w   = (const float*)d_in[7];
    const float* k_b   = (const float*)d_in[8];
    const float* v_w   = (const float*)d_in[9];
    const float* v_b   = (const float*)d_in[10];
    const float* p_w   = (const float*)d_in[11];
    const float* p_b   = (const float*)d_in[12];
    const float* w1    = (const float*)d_in[13];
    const float* b1    = (const float*)d_in[14];
    const float* w2    = (const float*)d_in[15];

    float* out_x    = (float*)d_out;                       // (nQ, B, DIM)
    float* out_attn = (float*)d_out + BB * NQ * DIM;       // (B, NH, nQ, nK)

    const int smem_bytes = SM_TOTAL_F * (int)sizeof(float);
    cudaFuncSetAttribute(k_attn, cudaFuncAttributeMaxDynamicSharedMemorySize, smem_bytes);

    k_tables<<<(NPTS * NCELL + 255) / 256, 256>>>(w1, b1, w2);
    k_qproj <<<BB * NQ / 8, 256>>>(query, q_w, q_b);
    k_kvproj<<<BB * NK / 16, 256>>>(key, k_w, k_b, v_w, v_b);
    k_attn  <<<BB * NQ, ATT_THREADS, smem_bytes>>>(refpt, xyz, out_attn);
    k_proj  <<<BB * NQ / 8, 256>>>(p_w, p_b, out_x);
}

// round 4
// speedup vs baseline: 1.5804x; 1.5804x over previous
#include <cuda_runtime.h>
#include <cuda_fp16.h>
#include <math.h>

#define BB 2
#define NQ 256
#define NK 2048
#define DIM 256
#define NH 8
#define HD 32
#define NPTS 8
#define NCELL 1000

#define ATT_THREADS 512
#define KPT (NK / ATT_THREADS)   // 4
#define SST (NK + 8)             // padded score row stride (floats)

// scratch (device globals — no allocation allowed)
__device__ __half g_tables[NPTS * NCELL * NH];  // [i][cell=z*100+y*10+x][h], fp16
__device__ float g_qproj[BB * NQ * DIM];
__device__ float g_kproj[BB * NK * HD];
__device__ float g_vproj[BB * NK * HD];
__device__ float g_xmid [BB * NQ * DIM];

// -------------------- CPB tables --------------------
__global__ void k_tables(const float* __restrict__ w1, const float* __restrict__ b1,
                         const float* __restrict__ w2) {
    int gid = blockIdx.x * blockDim.x + threadIdx.x;
    if (gid >= NPTS * NCELL) return;
    int i = gid / NCELL;
    int cell = gid % NCELL;
    int p = cell / 100, q = (cell / 10) % 10, r = cell % 10;
    const float step = 8.0f / 9.0f;
    float lp = -4.0f + p * step, lq = -4.0f + q * step, lr = -4.0f + r * step;
    const float* w1i = w1 + i * 3 * 128;
    const float* b1i = b1 + i * 128;
    const float* w2i = w2 + i * 128 * 8;
    float acc[8] = {0,0,0,0,0,0,0,0};
    for (int d = 0; d < 128; d++) {
        float h = lp * w1i[d] + lq * w1i[128 + d] + lr * w1i[256 + d] + b1i[d];
        h = fmaxf(h, 0.0f);
        const float* w2d = w2i + d * 8;
        #pragma unroll
        for (int hh = 0; hh < 8; hh++) acc[hh] += h * w2d[hh];
    }
    __half* out = g_tables + gid * 8;
    #pragma unroll
    for (int hh = 0; hh < 8; hh++) out[hh] = __float2half(acc[hh]);
}

// -------------------- Q projection (R2 version: 512 blocks) --------------------
__global__ void k_qproj(const float* __restrict__ query, const float* __restrict__ w,
                        const float* __restrict__ bias) {
    __shared__ float row[DIM];
    int rid = blockIdx.x;               // b*NQ + nq
    int b = rid >> 8, nq = rid & 255;
    int t = threadIdx.x;
    row[t] = query[(nq * BB + b) * DIM + t];   // query is (nQ, B, DIM)
    __syncthreads();
    float acc = bias[t];
    #pragma unroll 4
    for (int c = 0; c < DIM; c++) acc += row[c] * w[c * DIM + t];
    g_qproj[rid * DIM + t] = acc;
}

// -------------------- K/V projection (R2 version: 4096 blocks) --------------------
__global__ void k_kvproj(const float* __restrict__ key,
                         const float* __restrict__ kw, const float* __restrict__ kb,
                         const float* __restrict__ vw, const float* __restrict__ vb) {
    __shared__ float row[DIM];
    int rid = blockIdx.x;               // b*NK + kk
    int b = rid >> 11, kk = rid & 2047;
    int t = threadIdx.x;                // 64 threads
    for (int c = t; c < DIM; c += 64) row[c] = key[(kk * BB + b) * DIM + c];
    __syncthreads();
    int j = t & 31;
    const float* w  = (t < 32) ? kw : vw;
    float acc       = (t < 32) ? kb[j] : vb[j];
    #pragma unroll 4
    for (int c = 0; c < DIM; c++) acc += row[c] * w[c * HD + j];
    if (t < 32) g_kproj[rid * HD + j] = acc;
    else        g_vproj[rid * HD + j] = acc;
}

// -------------------- attention megakernel --------------------
__device__ __forceinline__ float xform(float dd) {
    float g = __log2f(fabsf(dd) * 512.0f + 1.0f) * (1.0f / 12.0f);
    return copysignf(g, dd);
}

__device__ __forceinline__ void axis_setup(float f, int scale, int* o, float* w) {
    float f0 = floorf(f);
    int i0 = (int)f0;
    float w1 = f - f0;
    int c0 = min(max(i0, 0), 9);
    int c1 = min(max(i0 + 1, 0), 9);
    o[0] = c0 * scale;
    o[1] = c1 * scale;
    w[0] = ((unsigned)i0 < 10u) ? 1.0f - w1 : 0.0f;
    w[1] = ((unsigned)(i0 + 1) < 10u) ? w1 : 0.0f;
}

// smem layout (floats):
//   s_tbl   : __half[64000] = 128000 B  (= 32000 floats) — reused as s_av after scores
//   s_scores: float[NH*SST] = 8*2056 = 16448 floats
//   s_q 256, s_rp 24, s_red 512
#define SM_TBL_F      32000
#define SM_SCORES_OFF SM_TBL_F
#define SM_Q_OFF      (SM_SCORES_OFF + NH * SST)
#define SM_RP_OFF     (SM_Q_OFF + DIM)
#define SM_RED_OFF    (SM_RP_OFF + 24)
#define SM_TOTAL_F    (SM_RED_OFF + 512)

__global__ void __launch_bounds__(ATT_THREADS, 1)
k_attn(const float* __restrict__ refpt, const float* __restrict__ xyz,
       float* __restrict__ out_attn) {
    extern __shared__ float sm[];
    __half* s_tbl   = (__half*)sm;
    float*  s_scores = sm + SM_SCORES_OFF;
    float*  s_q      = sm + SM_Q_OFF;
    float*  s_rp     = sm + SM_RP_OFF;
    float*  s_red    = sm + SM_RED_OFF;
    float4* s_av     = (float4*)sm;               // aliases s_tbl (dead after scores)

    int t = threadIdx.x;
    int bq = blockIdx.x;
    int b = bq >> 8, nq = bq & 255;

    if (t < DIM) s_q[t]  = g_qproj[bq * DIM + t];
    if (t < 24)  s_rp[t] = refpt[bq * 24 + t];

    // stage all 8 tables (fp16, 128000 B)
    {
        const uint4* src = (const uint4*)g_tables;
        uint4* dst = (uint4*)s_tbl;
        for (int idx = t; idx < 8000; idx += ATT_THREADS) dst[idx] = src[idx];
    }
    __syncthreads();

    const float4* s_q4 = (const float4*)s_q;
    const float scale = 0.17677669529663687f;     // 1/sqrt(32)

    float runmax[NH];
    #pragma unroll
    for (int h = 0; h < NH; h++) runmax[h] = -1e30f;

    // ---- QK^T + RPE : rolled m-loop (I$-friendly) ----
    #pragma unroll 1
    for (int m = 0; m < KPT; m++) {
        int k = t + m * ATT_THREADS;
        const float* kv = g_kproj + (b * NK + k) * HD;
        float kvv[HD];
        #pragma unroll
        for (int d = 0; d < HD; d += 4) {
            float4 f = *(const float4*)(kv + d);
            kvv[d] = f.x; kvv[d+1] = f.y; kvv[d+2] = f.z; kvv[d+3] = f.w;
        }
        const float* xv = xyz + (b * NK + k) * 3;
        float kx = xv[0], ky = xv[1], kz = xv[2];

        float acc[NH];
        #pragma unroll
        for (int h = 0; h < NH; h++) {
            float a = 0.f;
            #pragma unroll
            for (int d4 = 0; d4 < HD / 4; d4++) {
                float4 q = s_q4[h * (HD / 4) + d4];
                a += q.x * kvv[d4 * 4 + 0];
                a += q.y * kvv[d4 * 4 + 1];
                a += q.z * kvv[d4 * 4 + 2];
                a += q.w * kvv[d4 * 4 + 3];
            }
            acc[h] = a * scale;
        }

        __half2 hacc0 = __float2half2_rn(0.f);
        __half2 hacc1 = hacc0, hacc2 = hacc0, hacc3 = hacc0;
        #pragma unroll 2
        for (int i = 0; i < NPTS; i++) {
            float gx = xform(s_rp[i*3+0] - kx);
            float gy = xform(s_rp[i*3+1] - ky);
            float gz = xform(s_rp[i*3+2] - kz);
            float fx = fmaf(gx, 4.5f, 4.5f);
            float fy = fmaf(gy, 4.5f, 4.5f);
            float fz = fmaf(gz, 4.5f, 4.5f);
            int oxa[2], oya[2], oza[2];
            float wxa[2], wya[2], wza[2];
            axis_setup(fx, NH,       oxa, wxa);
            axis_setup(fy, NH * 10,  oya, wya);
            axis_setup(fz, NH * 100, oza, wza);
            float wzy[4] = {wza[0]*wya[0], wza[0]*wya[1], wza[1]*wya[0], wza[1]*wya[1]};
            int ozy[4];
            ozy[0] = oza[0]+oya[0]; ozy[1] = oza[0]+oya[1];
            ozy[2] = oza[1]+oya[0]; ozy[3] = oza[1]+oya[1];
            const __half* base = s_tbl + i * (NCELL * NH);
            uint4 raw[8];
            #pragma unroll
            for (int c = 0; c < 8; c++)
                raw[c] = *(const uint4*)(base + ozy[c >> 1] + oxa[c & 1]);
            #pragma unroll
            for (int c = 0; c < 8; c++) {
                float w = wzy[c >> 1] * wxa[c & 1];
                __half2 wh = __float2half2_rn(w);
                hacc0 = __hfma2(wh, *(const __half2*)&raw[c].x, hacc0);
                hacc1 = __hfma2(wh, *(const __half2*)&raw[c].y, hacc1);
                hacc2 = __hfma2(wh, *(const __half2*)&raw[c].z, hacc2);
                hacc3 = __hfma2(wh, *(const __half2*)&raw[c].w, hacc3);
            }
        }
        float2 f0 = __half22float2(hacc0);
        float2 f1 = __half22float2(hacc1);
        float2 f2 = __half22float2(hacc2);
        float2 f3 = __half22float2(hacc3);
        acc[0] += f0.x; acc[1] += f0.y;
        acc[2] += f1.x; acc[3] += f1.y;
        acc[4] += f2.x; acc[5] += f2.y;
        acc[6] += f3.x; acc[7] += f3.y;

        #pragma unroll
        for (int h = 0; h < NH; h++) {
            s_scores[h * SST + k] = acc[h];
            runmax[h] = fmaxf(runmax[h], acc[h]);
        }
    }
    __syncthreads();

    // ---- softmax: block max ----
    int lane = t & 31, wid = t >> 5;  // 16 warps
    #pragma unroll
    for (int h = 0; h < NH; h++) {
        float v = runmax[h];
        #pragma unroll
        for (int o = 16; o; o >>= 1) v = fmaxf(v, __shfl_xor_sync(0xffffffffu, v, o));
        if (lane == 0) s_red[h * 16 + wid] = v;
    }
    __syncthreads();
    if (t < NH) {
        float v = s_red[t * 16];
        for (int w2 = 1; w2 < 16; w2++) v = fmaxf(v, s_red[t * 16 + w2]);
        s_red[128 + t] = v;
    }
    __syncthreads();

    // ---- exp sweep (float4, k = 4t) ----
    #pragma unroll
    for (int h = 0; h < NH; h++) {
        float mh = s_red[128 + h];
        float4* p = (float4*)&s_scores[h * SST + 4 * t];
        float4 v = *p;
        v.x = __expf(v.x - mh); v.y = __expf(v.y - mh);
        v.z = __expf(v.z - mh); v.w = __expf(v.w - mh);
        *p = v;
        float s = (v.x + v.y) + (v.z + v.w);
        #pragma unroll
        for (int o = 16; o; o >>= 1) s += __shfl_xor_sync(0xffffffffu, s, o);
        if (lane == 0) s_red[h * 16 + wid] = s;
    }
    __syncthreads();
    if (t < NH) {
        float v = 0.f;
        for (int w2 = 0; w2 < 16; w2++) v += s_red[t * 16 + w2];
        s_red[136 + t] = 1.0f / v;
    }
    __syncthreads();

    // ---- normalized attn writeback (float4) ----
    #pragma unroll
    for (int h = 0; h < NH; h++) {
        float r = s_red[136 + h];
        float4 v = *(const float4*)&s_scores[h * SST + 4 * t];
        v.x *= r; v.y *= r; v.z *= r; v.w *= r;
        *(float4*)&out_attn[((size_t)(b * NH + h) * NQ + nq) * NK + 4 * t] = v;
    }
    __syncthreads();   // also: table smem now dead, reuse as s_av

    // ---- AV: thread = (kslice, head, d-group) ----
    {
        int ks = t >> 6;            // 0..7
        int rem = t & 63;
        int h  = rem >> 3;          // 0..7
        int dg = rem & 7;           // 0..7 (4 dims each)
        const float* vbase = g_vproj + b * NK * HD + dg * 4;
        const float* prow = s_scores + h * SST;
        float4 a0 = {0,0,0,0}, a1 = {0,0,0,0};
        int k0 = ks * 256;
        #pragma unroll 2
        for (int kk = 0; kk < 256; kk += 2) {
            int ka = k0 + kk, kb2 = k0 + kk + 1;
            float pa = prow[ka], pb = prow[kb2];
            float4 va = *(const float4*)(vbase + ka * HD);
            float4 vb2 = *(const float4*)(vbase + kb2 * HD);
            a0.x += pa * va.x;  a0.y += pa * va.y;  a0.z += pa * va.z;  a0.w += pa * va.w;
            a1.x += pb * vb2.x; a1.y += pb * vb2.y; a1.z += pb * vb2.z; a1.w += pb * vb2.w;
        }
        a0.x += a1.x; a0.y += a1.y; a0.z += a1.z; a0.w += a1.w;
        s_av[t] = a0;
    }
    __syncthreads();
    if (t < 256) {
        int h = t >> 5, d = t & 31;
        int dg = d >> 2, c = d & 3;
        float acc = 0.f;
        #pragma unroll
        for (int ks = 0; ks < 8; ks++)
            acc += ((const float*)&s_av[ks * 64 + h * 8 + dg])[c];
        acc *= s_red[136 + h];
        g_xmid[bq * DIM + t] = acc;
    }
}

// -------------------- output projection (R2 version: 512 blocks) --------------------
__global__ void k_proj(const float* __restrict__ w, const float* __restrict__ bias,
                       float* __restrict__ out_x) {
    __shared__ float row[DIM];
    int rid = blockIdx.x;               // b*NQ + nq
    int b = rid >> 8, nq = rid & 255;
    int t = threadIdx.x;
    row[t] = g_xmid[rid * DIM + t];
    __syncthreads();
    float acc = bias[t];
    #pragma unroll 4
    for (int c = 0; c < DIM; c++) acc += row[c] * w[c * DIM + t];
    out_x[(nq * BB + b) * DIM + t] = acc;
}

// -------------------- launch --------------------
extern "C" void kernel_launch(void* const* d_in, const int* in_sizes, int n_in,
                              void* d_out, int out_size) {
    const float* query = (const float*)d_in[0];
    const float* key   = (const float*)d_in[1];
    const float* refpt = (const float*)d_in[2];
    const float* xyz   = (const float*)d_in[4];
    const float* q_w   = (const float*)d_in[5];
    const float* q_b   = (const float*)d_in[6];
    const float* k_w   = (const float*)d_in[7];
    const float* k_b   = (const float*)d_in[8];
    const float* v_w   = (const float*)d_in[9];
    const float* v_b   = (const float*)d_in[10];
    const float* p_w   = (const float*)d_in[11];
    const float* p_b   = (const float*)d_in[12];
    const float* w1    = (const float*)d_in[13];
    const float* b1    = (const float*)d_in[14];
    const float* w2    = (const float*)d_in[15];

    float* out_x    = (float*)d_out;                       // (nQ, B, DIM)
    float* out_attn = (float*)d_out + BB * NQ * DIM;       // (B, NH, nQ, nK)

    const int smem_bytes = SM_TOTAL_F * (int)sizeof(float);
    cudaFuncSetAttribute(k_attn, cudaFuncAttributeMaxDynamicSharedMemorySize, smem_bytes);

    k_tables<<<(NPTS * NCELL + 255) / 256, 256>>>(w1, b1, w2);
    k_qproj <<<BB * NQ, 256>>>(query, q_w, q_b);
    k_kvproj<<<BB * NK, 64>>>(key, k_w, k_b, v_w, v_b);
    k_attn  <<<BB * NQ, ATT_THREADS, smem_bytes>>>(refpt, xyz, out_attn);
    k_proj  <<<BB * NQ, 256>>>(p_w, p_b, out_x);
}